// round 9
// baseline (speedup 1.0000x reference)
#include <cuda_runtime.h>
#include <cuda_bf16.h>
#include <cstdint>

#define NROWS   131072
#define D_IN    512
#define DH      128
#define NCODE   256
#define BETA    0.25

// ---------------- scratch ----------------
__device__ __nv_bfloat16  g_wenc[(size_t)DH * D_IN];      // 128 x 512
__device__ __nv_bfloat16  g_wdec[(size_t)D_IN * DH];      // 512 x 128
__device__ __nv_bfloat16  g_cb[3 * NCODE * DH];           // 3 x 256 x 128
__device__ float          g_cn[3 * NCODE];
__device__ double g_rq;
__device__ double g_recon;
__device__ int    g_used[3 * NCODE];

// ---------------- helpers ----------------
__device__ __forceinline__ uint32_t s2u(const void* p) {
    uint32_t a;
    asm("{ .reg .u64 t; cvta.to.shared.u64 t, %1; cvt.u32.u64 %0, t; }" : "=r"(a) : "l"(p));
    return a;
}
__device__ __forceinline__ void ldsm4(uint32_t* r, uint32_t addr) {
    asm volatile("ldmatrix.sync.aligned.m8n8.x4.shared.b16 {%0,%1,%2,%3}, [%4];"
        : "=r"(r[0]), "=r"(r[1]), "=r"(r[2]), "=r"(r[3]) : "r"(addr));
}
__device__ __forceinline__ void mma16816(float* c, const uint32_t* a, const uint32_t* b) {
    asm volatile("mma.sync.aligned.m16n8k16.row.col.f32.bf16.bf16.f32 "
        "{%0,%1,%2,%3}, {%4,%5,%6,%7}, {%8,%9}, {%0,%1,%2,%3};"
        : "+f"(c[0]), "+f"(c[1]), "+f"(c[2]), "+f"(c[3])
        : "r"(a[0]), "r"(a[1]), "r"(a[2]), "r"(a[3]), "r"(b[0]), "r"(b[1]));
}
__device__ __forceinline__ void st_bf2(__nv_bfloat16* p, float a, float b) {
    __nv_bfloat162 v = __floats2bfloat162_rn(a, b);
    *(uint32_t*)p = *(uint32_t*)&v;
}
__device__ __forceinline__ void cp16(uint32_t dst, const void* src) {
    asm volatile("cp.async.cg.shared.global [%0], [%1], 16;" :: "r"(dst), "l"(src));
}
__device__ __forceinline__ void cp_commit() {
    asm volatile("cp.async.commit_group;" ::: "memory");
}
template<int N> __device__ __forceinline__ void cp_wait() {
    asm volatile("cp.async.wait_group %0;" :: "n"(N) : "memory");
}

// ---------------- init / norms / convert ----------------
__global__ void k_init() {
    int t = threadIdx.x;
    if (t == 0) { g_rq = 0.0; g_recon = 0.0; }
    if (t < 3 * NCODE) g_used[t] = 0;
}
__global__ void k_norms(const float* __restrict__ cb0,
                        const float* __restrict__ cb1,
                        const float* __restrict__ cb2) {
    const float* cbs[3] = {cb0, cb1, cb2};
    const float* cb = cbs[blockIdx.x];
    int t = threadIdx.x;
    float s = 0.f;
#pragma unroll
    for (int q = 0; q < 32; q++) {
        float4 v = *(const float4*)(cb + (size_t)t * DH + q * 4);
        s += v.x * v.x + v.y * v.y + v.z * v.z + v.w * v.w;
    }
    g_cn[blockIdx.x * NCODE + t] = s;
}
__global__ void k_cvt(const float* __restrict__ we, const float* __restrict__ wd,
                      const float* __restrict__ c0, const float* __restrict__ c1,
                      const float* __restrict__ c2) {
    int i = blockIdx.x * 256 + threadIdx.x;
    const float* src; uint32_t* dst; int off;
    if (i < 32768)       { src = we; dst = (uint32_t*)g_wenc;         off = i; }
    else if (i < 65536)  { src = wd; dst = (uint32_t*)g_wdec;         off = i - 32768; }
    else if (i < 81920)  { src = c0; dst = (uint32_t*)g_cb;           off = i - 65536; }
    else if (i < 98304)  { src = c1; dst = (uint32_t*)g_cb + 16384;   off = i - 81920; }
    else                 { src = c2; dst = (uint32_t*)g_cb + 32768;   off = i - 98304; }
    float2 v = ((const float2*)src)[off];
    __nv_bfloat162 p = __floats2bfloat162_rn(v.x, v.y);
    dst[off] = *(uint32_t*)&p;
}

// =========================================================================
// Fused kernel, 64 rows/CTA, 512 thr, 2 CTAs/SM.
// smem map (bytes):
//  sA  (rem bf16 64x136)     @ 0       17408
//  sR  (restored bf16 64x136)@ 17408   17408
//  RG  (shared region)       @ 34816   69632
//     GEMM1: sE emb 64x72 @+0 (9216), wenc buf0 @+9216, buf1 @+27648 (18432 ea)
//     RQ:    cb slab buf0 @+0 (34816: 128 codes x 272B), buf1 @+34816
//     recon: wdec buf0 @+0 (17408: 64 x 272B), buf1 @+34816
//  cn f32[256]               @ 104448  1024
//  bestv f32[4][64]          @ 105472  1024
//  besti i32[4][64]          @ 106496  1024
//  idx i32[64]               @ 107520  256
// total 107776 -> 2 CTAs/SM
// =========================================================================
#define F_SA   0
#define F_SR   17408
#define F_RG   34816
#define F_CN   104448
#define F_BV   105472
#define F_BI   106496
#define F_IDX  107520
#define F_SMEM 107776

__global__ __launch_bounds__(512, 2) void k_fused(const float* __restrict__ emb,
                                                  const float* __restrict__ cb0,
                                                  const float* __restrict__ cb1,
                                                  const float* __restrict__ cb2) {
    extern __shared__ char smc[];
    __nv_bfloat16* sA = (__nv_bfloat16*)(smc + F_SA);
    __nv_bfloat16* sR = (__nv_bfloat16*)(smc + F_SR);
    __nv_bfloat16* sE = (__nv_bfloat16*)(smc + F_RG);
    float* cn_s  = (float*)(smc + F_CN);
    float* bestv = (float*)(smc + F_BV);
    int*   besti = (int*)(smc + F_BI);
    int*   idx_s = (int*)(smc + F_IDX);
    uint32_t aBase = s2u(smc);
    uint32_t aSA = aBase + F_SA, aSR = aBase + F_SR, aRG = aBase + F_RG;
    uint32_t aE = aRG;                                   // emb staging (GEMM1)
    uint32_t aW[2] = {aRG + 9216, aRG + 27648};          // wenc bufs
    uint32_t aCBB[2] = {aRG, aRG + 34816};               // cb slab bufs / wdec bufs

    int t = threadIdx.x, lane = t & 31, wid = t >> 5;
    int wr = wid >> 2, wc = wid & 3;                     // 4 row-groups x 4 col-groups
    int row0 = blockIdx.x * 64;

    // ---- issue wenc chunk 0 ----
#pragma unroll
    for (int i = 0; i < 2; i++) {
        int q = i * 512 + t;
        int row = q >> 3, c16 = q & 7;
        cp16(aW[0] + row * 144 + c16 * 16, g_wenc + (size_t)row * D_IN + c16 * 8);
    }
    cp_commit();

    // ---- emb chunk 0 register prefetch ----
    float2 pe[4];
#pragma unroll
    for (int i = 0; i < 4; i++) {
        int idx = i * 512 + t;
        int row = idx >> 5, cp = idx & 31;
        pe[i] = *(const float2*)(emb + (size_t)(row0 + row) * D_IN + cp * 2);
    }

    // =========== Phase 1: latent = emb @ Wenc^T ===========
    float acc1[4][4];
#pragma unroll
    for (int nt = 0; nt < 4; nt++)
#pragma unroll
        for (int j = 0; j < 4; j++) acc1[nt][j] = 0.f;

    for (int c = 0; c < 8; c++) {
        cp_wait<0>();
        __syncthreads();
        if (c < 7) {
            int buf = (c + 1) & 1;
#pragma unroll
            for (int i = 0; i < 2; i++) {
                int q = i * 512 + t;
                int row = q >> 3, c16 = q & 7;
                cp16(aW[buf] + row * 144 + c16 * 16,
                     g_wenc + (size_t)row * D_IN + (c + 1) * 64 + c16 * 8);
            }
            cp_commit();
        }
#pragma unroll
        for (int i = 0; i < 4; i++) {
            int idx = i * 512 + t;
            int row = idx >> 5, cp = idx & 31;
            st_bf2((__nv_bfloat16*)(smc + F_RG) + row * 72 + cp * 2, pe[i].x, pe[i].y);
        }
        if (c < 7) {
#pragma unroll
            for (int i = 0; i < 4; i++) {
                int idx = i * 512 + t;
                int row = idx >> 5, cp = idx & 31;
                pe[i] = *(const float2*)(emb + (size_t)(row0 + row) * D_IN + (c + 1) * 64 + cp * 2);
            }
        }
        __syncthreads();
        uint32_t aWc = aW[c & 1];
#pragma unroll
        for (int kt = 0; kt < 4; kt++) {
            uint32_t af[4], bfr[2][4];
            ldsm4(af, aE + ((wr * 16 + (lane & 15)) * 72 + kt * 16 + (lane >> 4) * 8) * 2);
#pragma unroll
            for (int np = 0; np < 2; np++) {
                int n = wc * 32 + np * 16 + (lane & 7) + ((lane >> 4) & 1) * 8;
                ldsm4(bfr[np], aWc + (n * 72 + kt * 16 + ((lane >> 3) & 1) * 8) * 2);
            }
#pragma unroll
            for (int np = 0; np < 2; np++) {
                mma16816(acc1[2 * np],     af, &bfr[np][0]);
                mma16816(acc1[2 * np + 1], af, &bfr[np][2]);
            }
        }
    }
    __syncthreads();          // all MMAs done reading region
    // latent -> sA
#pragma unroll
    for (int nt = 0; nt < 4; nt++) {
        int row = wr * 16 + (lane >> 2);
        int col = wc * 32 + nt * 8 + (lane & 3) * 2;
        st_bf2(&sA[row * 136 + col],       acc1[nt][0], acc1[nt][1]);
        st_bf2(&sA[(row + 8) * 136 + col], acc1[nt][2], acc1[nt][3]);
    }
    // issue cb slabs j=0 (buf0), j=1 (buf1)
#pragma unroll
    for (int j0 = 0; j0 < 2; j0++) {
#pragma unroll
        for (int i = 0; i < 4; i++) {
            int q = i * 512 + t;
            int row = q >> 4, c16 = q & 15;
            cp16(aCBB[j0] + row * 272 + c16 * 16,
                 g_cb + (size_t)(j0 * 128 + row) * DH + c16 * 8);
        }
        cp_commit();
    }

    // =========== Phase 2: 3-level RQ, streamed codebook slabs ===========
    float rql = 0.f;
    const float* cbs[3] = {cb0, cb1, cb2};
    float best[2]; int bidx[2];

    for (int j = 0; j < 6; j++) {
        int L = j >> 1, h = j & 1;
        uint32_t aCBc = aCBB[j & 1];
        cp_wait<1>();
        if (h == 0 && t < 256) cn_s[t] = g_cn[L * NCODE + t];
        __syncthreads();      // slab visible; buffer's prior readers done
        if (h == 0) { best[0] = best[1] = 3.4e38f; bidx[0] = bidx[1] = 0; }

        float acc[4][4];
#pragma unroll
        for (int nt = 0; nt < 4; nt++)
#pragma unroll
            for (int q = 0; q < 4; q++) acc[nt][q] = 0.f;
#pragma unroll
        for (int kt = 0; kt < 8; kt++) {
            uint32_t af[4], bfr[2][4];
            ldsm4(af, aSA + ((wr * 16 + (lane & 15)) * 136 + kt * 16 + (lane >> 4) * 8) * 2);
#pragma unroll
            for (int np = 0; np < 2; np++) {
                int n = wc * 32 + np * 16 + (lane & 7) + ((lane >> 4) & 1) * 8;
                ldsm4(bfr[np], aCBc + (n * 136 + kt * 16 + ((lane >> 3) & 1) * 8) * 2);
            }
#pragma unroll
            for (int np = 0; np < 2; np++) {
                mma16816(acc[2 * np],     af, &bfr[np][0]);
                mma16816(acc[2 * np + 1], af, &bfr[np][2]);
            }
        }
#pragma unroll
        for (int nt = 0; nt < 4; nt++) {
            int col = h * 128 + wc * 32 + nt * 8 + (lane & 3) * 2;
            float c0 = cn_s[col], c1 = cn_s[col + 1];
#pragma unroll
            for (int s = 0; s < 2; s++) {
                float k0 = fmaf(-2.f, acc[nt][s * 2],     c0);
                float k1 = fmaf(-2.f, acc[nt][s * 2 + 1], c1);
                if (k0 < best[s]) { best[s] = k0; bidx[s] = col; }
                if (k1 < best[s]) { best[s] = k1; bidx[s] = col + 1; }
            }
        }
        __syncthreads();      // buffer free to overwrite
        if (j + 2 < 6) {      // next cb slab -> this buffer
#pragma unroll
            for (int i = 0; i < 4; i++) {
                int q = i * 512 + t;
                int row = q >> 4, c16 = q & 15;
                cp16(aCBc + row * 272 + c16 * 16,
                     g_cb + (size_t)((j + 2) >> 1) * NCODE * DH
                          + (size_t)(((j + 2) & 1) * 128 + row) * DH + c16 * 8);
            }
            cp_commit();
        } else {              // wdec pass (j-4) -> this buffer
            int p = j - 4;
#pragma unroll
            for (int i = 0; i < 2; i++) {
                int q = i * 512 + t;
                int row = q >> 4, c16 = q & 15;
                cp16(aCBB[p & 1] + row * 272 + c16 * 16,
                     g_wdec + (size_t)(p * 64 + row) * DH + c16 * 8);
            }
            cp_commit();
        }

        if (h == 1) {
            const float* cbg = cbs[L];
            // quad reduce + write
#pragma unroll
            for (int s = 0; s < 2; s++) {
                float bv = best[s]; int bi = bidx[s];
#pragma unroll
                for (int off = 1; off < 4; off <<= 1) {
                    float ov = __shfl_xor_sync(0xffffffffu, bv, off);
                    int   oi = __shfl_xor_sync(0xffffffffu, bi, off);
                    if (ov < bv || (ov == bv && oi < bi)) { bv = ov; bi = oi; }
                }
                if ((lane & 3) == 0) {
                    int row = wr * 16 + (lane >> 2) + s * 8;
                    bestv[wc * 64 + row] = bv;
                    besti[wc * 64 + row] = bi;
                }
            }
            __syncthreads();
            if (t < 64) {
                float bv = bestv[t]; int bi = besti[t];
#pragma unroll
                for (int w = 1; w < 4; w++) {
                    float ov = bestv[w * 64 + t]; int oi = besti[w * 64 + t];
                    if (ov < bv || (ov == bv && oi < bi)) { bv = ov; bi = oi; }
                }
                idx_s[t] = bi;
                g_used[L * NCODE + bi] = 1;
            }
            __syncthreads();
            // remainder + restored update (fp32 codebook gather from global)
#pragma unroll
            for (int i = 0; i < 4; i++) {
                int r = wid * 4 + i;
                int ci = idx_s[r];
                float4 cv = *(const float4*)(cbg + (size_t)ci * DH + lane * 4);
                uint32_t p0 = *(uint32_t*)&sA[r * 136 + lane * 4];
                uint32_t p1 = *(uint32_t*)&sA[r * 136 + lane * 4 + 2];
                __nv_bfloat162 b0 = *(__nv_bfloat162*)&p0;
                __nv_bfloat162 b1 = *(__nv_bfloat162*)&p1;
                float n0 = __low2float(b0)  - cv.x;
                float n1 = __high2float(b0) - cv.y;
                float n2 = __low2float(b1)  - cv.z;
                float n3 = __high2float(b1) - cv.w;
                rql += n0 * n0 + n1 * n1 + n2 * n2 + n3 * n3;
                st_bf2(&sA[r * 136 + lane * 4],     n0, n1);
                st_bf2(&sA[r * 136 + lane * 4 + 2], n2, n3);
                float r0 = cv.x, r1 = cv.y, r2 = cv.z, r3 = cv.w;
                if (L > 0) {
                    uint32_t q0 = *(uint32_t*)&sR[r * 136 + lane * 4];
                    uint32_t q1 = *(uint32_t*)&sR[r * 136 + lane * 4 + 2];
                    __nv_bfloat162 rb0 = *(__nv_bfloat162*)&q0;
                    __nv_bfloat162 rb1 = *(__nv_bfloat162*)&q1;
                    r0 += __low2float(rb0);  r1 += __high2float(rb0);
                    r2 += __low2float(rb1);  r3 += __high2float(rb1);
                }
                st_bf2(&sR[r * 136 + lane * 4],     r0, r1);
                st_bf2(&sR[r * 136 + lane * 4 + 2], r2, r3);
            }
        }
    }

    // =========== Phase 3: recon GEMM + fused MSE (8 passes of 64 N) ===========
    float local = 0.f;
    for (int p = 0; p < 8; p++) {
        uint32_t aDc = aCBB[p & 1];
        cp_wait<1>();
        __syncthreads();      // wdec slab visible; sR updates visible (first iter)
        float accR[2][4];
#pragma unroll
        for (int nt = 0; nt < 2; nt++)
#pragma unroll
            for (int q = 0; q < 4; q++) accR[nt][q] = 0.f;
#pragma unroll
        for (int kt = 0; kt < 8; kt++) {
            uint32_t af[4], bfr[4];
            ldsm4(af, aSR + ((wr * 16 + (lane & 15)) * 136 + kt * 16 + (lane >> 4) * 8) * 2);
            int n = wc * 16 + (lane & 7) + ((lane >> 4) & 1) * 8;
            ldsm4(bfr, aDc + (n * 136 + kt * 16 + ((lane >> 3) & 1) * 8) * 2);
            mma16816(accR[0], af, &bfr[0]);
            mma16816(accR[1], af, &bfr[2]);
        }
        __syncthreads();      // done reading buffer
        if (p + 2 < 8) {
#pragma unroll
            for (int i = 0; i < 2; i++) {
                int q = i * 512 + t;
                int row = q >> 4, c16 = q & 15;
                cp16(aDc + row * 272 + c16 * 16,
                     g_wdec + (size_t)((p + 2) * 64 + row) * DH + c16 * 8);
            }
            cp_commit();
        }
#pragma unroll
        for (int nt = 0; nt < 2; nt++) {
            int row = row0 + wr * 16 + (lane >> 2);
            int col = p * 64 + wc * 16 + nt * 8 + (lane & 3) * 2;
            float2 e0 = *(const float2*)(emb + (size_t)row * D_IN + col);
            float2 e1 = *(const float2*)(emb + (size_t)(row + 8) * D_IN + col);
            float d0 = accR[nt][0] - e0.x;
            float d1 = accR[nt][1] - e0.y;
            float d2 = accR[nt][2] - e1.x;
            float d3 = accR[nt][3] - e1.y;
            local += d0 * d0 + d1 * d1 + d2 * d2 + d3 * d3;
        }
    }

    // ---- reductions ----
#pragma unroll
    for (int off = 16; off > 0; off >>= 1) {
        rql   += __shfl_xor_sync(0xffffffffu, rql, off);
        local += __shfl_xor_sync(0xffffffffu, local, off);
    }
    if (lane == 0) {
        atomicAdd(&g_rq, (double)rql);
        atomicAdd(&g_recon, (double)local);
    }
}

// ---------------- finalize ----------------
__global__ void k_finalize(float* __restrict__ out, int out_size) {
    __shared__ int cnt[3];
    int t = threadIdx.x;
    if (t < 3) cnt[t] = 0;
    __syncthreads();
    if (t < 3 * NCODE) { if (g_used[t]) atomicAdd(&cnt[t / NCODE], 1); }
    __syncthreads();
    if (t == 0) {
        double recon = g_recon / ((double)NROWS * (double)D_IN);
        double rq    = (1.0 + BETA) * g_rq / ((double)NROWS * (double)DH);
        float rf = (float)recon, qf = (float)rq;
        if (out_size > 0) out[0] = rf + qf;
        if (out_size > 1) out[1] = rf;
        if (out_size > 2) out[2] = qf;
        if (out_size > 3) out[3] = (float)cnt[0];
        if (out_size > 4) out[4] = (float)cnt[1];
        if (out_size > 5) out[5] = (float)cnt[2];
    }
    for (int i = 6 + t; i < out_size; i += blockDim.x) out[i] = 0.f;
}

// ---------------- launch ----------------
extern "C" void kernel_launch(void* const* d_in, const int* in_sizes, int n_in,
                              void* d_out, int out_size) {
    const float* emb  = (const float*)d_in[0];
    const float* Wenc = (const float*)d_in[1];
    const float* Wdec = (const float*)d_in[2];
    const float* cb0  = (const float*)d_in[3];
    const float* cb1  = (const float*)d_in[4];
    const float* cb2  = (const float*)d_in[5];

    cudaFuncSetAttribute(k_fused, cudaFuncAttributeMaxDynamicSharedMemorySize, F_SMEM);

    k_init<<<1, 768>>>();
    k_norms<<<3, 256>>>(cb0, cb1, cb2);
    k_cvt<<<448, 256>>>(Wenc, Wdec, cb0, cb1, cb2);
    k_fused<<<NROWS / 64, 512, F_SMEM>>>(emb, cb0, cb1, cb2);
    k_finalize<<<1, 768>>>((float*)d_out, out_size);
}

// round 12
// speedup vs baseline: 1.1453x; 1.1453x over previous
#include <cuda_runtime.h>
#include <cuda_bf16.h>
#include <cstdint>

#define NROWS   131072
#define D_IN    512
#define DH      128
#define NCODE   256
#define BETA    0.25

// ---------------- scratch ----------------
__device__ __nv_bfloat16  g_wenc[(size_t)DH * D_IN];      // 128 x 512
__device__ __nv_bfloat16  g_wdec[(size_t)D_IN * DH];      // 512 x 128
__device__ __nv_bfloat16  g_cb[3 * NCODE * DH];           // 3 x 256 x 128
__device__ float          g_cn[3 * NCODE];
__device__ double g_rq;
__device__ double g_recon;
__device__ int    g_used[3 * NCODE];

// ---------------- helpers ----------------
__device__ __forceinline__ uint32_t s2u(const void* p) {
    uint32_t a;
    asm("{ .reg .u64 t; cvta.to.shared.u64 t, %1; cvt.u32.u64 %0, t; }" : "=r"(a) : "l"(p));
    return a;
}
__device__ __forceinline__ void ldsm4(uint32_t* r, uint32_t addr) {
    asm volatile("ldmatrix.sync.aligned.m8n8.x4.shared.b16 {%0,%1,%2,%3}, [%4];"
        : "=r"(r[0]), "=r"(r[1]), "=r"(r[2]), "=r"(r[3]) : "r"(addr));
}
__device__ __forceinline__ void mma16816(float* c, const uint32_t* a, const uint32_t* b) {
    asm volatile("mma.sync.aligned.m16n8k16.row.col.f32.bf16.bf16.f32 "
        "{%0,%1,%2,%3}, {%4,%5,%6,%7}, {%8,%9}, {%0,%1,%2,%3};"
        : "+f"(c[0]), "+f"(c[1]), "+f"(c[2]), "+f"(c[3])
        : "r"(a[0]), "r"(a[1]), "r"(a[2]), "r"(a[3]), "r"(b[0]), "r"(b[1]));
}
__device__ __forceinline__ void st_bf2(__nv_bfloat16* p, float a, float b) {
    __nv_bfloat162 v = __floats2bfloat162_rn(a, b);
    *(uint32_t*)p = *(uint32_t*)&v;
}
__device__ __forceinline__ void cp16(uint32_t dst, const void* src) {
    asm volatile("cp.async.cg.shared.global [%0], [%1], 16;" :: "r"(dst), "l"(src));
}
__device__ __forceinline__ void cp_commit() {
    asm volatile("cp.async.commit_group;" ::: "memory");
}
template<int N> __device__ __forceinline__ void cp_wait() {
    asm volatile("cp.async.wait_group %0;" :: "n"(N) : "memory");
}

// ---------------- init / norms / convert ----------------
__global__ void k_init() {
    int t = threadIdx.x;
    if (t == 0) { g_rq = 0.0; g_recon = 0.0; }
    if (t < 3 * NCODE) g_used[t] = 0;
}
__global__ void k_norms(const float* __restrict__ cb0,
                        const float* __restrict__ cb1,
                        const float* __restrict__ cb2) {
    const float* cbs[3] = {cb0, cb1, cb2};
    const float* cb = cbs[blockIdx.x];
    int t = threadIdx.x;
    float s = 0.f;
#pragma unroll
    for (int q = 0; q < 32; q++) {
        float4 v = *(const float4*)(cb + (size_t)t * DH + q * 4);
        s += v.x * v.x + v.y * v.y + v.z * v.z + v.w * v.w;
    }
    g_cn[blockIdx.x * NCODE + t] = s;
}
__global__ void k_cvt(const float* __restrict__ we, const float* __restrict__ wd,
                      const float* __restrict__ c0, const float* __restrict__ c1,
                      const float* __restrict__ c2) {
    int i = blockIdx.x * 256 + threadIdx.x;
    const float* src; uint32_t* dst; int off;
    if (i < 32768)       { src = we; dst = (uint32_t*)g_wenc;         off = i; }
    else if (i < 65536)  { src = wd; dst = (uint32_t*)g_wdec;         off = i - 32768; }
    else if (i < 81920)  { src = c0; dst = (uint32_t*)g_cb;           off = i - 65536; }
    else if (i < 98304)  { src = c1; dst = (uint32_t*)g_cb + 16384;   off = i - 81920; }
    else                 { src = c2; dst = (uint32_t*)g_cb + 32768;   off = i - 98304; }
    float2 v = ((const float2*)src)[off];
    __nv_bfloat162 p = __floats2bfloat162_rn(v.x, v.y);
    dst[off] = *(uint32_t*)&p;
}

// =========================================================================
// Fused kernel, 128 rows/CTA, 256 thr (8 warps as 2 row-groups x 4 col-groups),
// warp tile 64x32, 2 CTAs/SM.
// smem map (bytes):
//  sA (rem -> restored, bf16 128x136) @ 0       34816
//  RG (shared staging region)         @ 34816   69632
//     GEMM1: emb 128x72 @+0 (18432), wenc buf0 @+18432, buf1 @+36864
//     RQ:    cb slab (128 codes x 272B = 34816) buf0 @+0, buf1 @+34816
//     recon: wdec slab (128 x 272B) buf0 @+0, buf1 @+34816
//  cn f32[256]     @ 104448  1024
//  bestv f32[4][128] @ 105472 2048
//  besti i32[4][128] @ 107520 2048
//  idx i32[3][128]   @ 109568 1536
// total 111104 -> 2 CTAs/SM, regs capped at 128
// =========================================================================
#define F_SA   0
#define F_RG   34816
#define F_CN   104448
#define F_BV   105472
#define F_BI   107520
#define F_IDX  109568
#define F_SMEM 111104

__global__ __launch_bounds__(256, 2) void k_fused(const float* __restrict__ emb,
                                                  const float* __restrict__ cb0,
                                                  const float* __restrict__ cb1,
                                                  const float* __restrict__ cb2) {
    extern __shared__ char smc[];
    __nv_bfloat16* sA = (__nv_bfloat16*)(smc + F_SA);
    __nv_bfloat16* sE = (__nv_bfloat16*)(smc + F_RG);
    float* cn_s  = (float*)(smc + F_CN);
    float* bestv = (float*)(smc + F_BV);
    int*   besti = (int*)(smc + F_BI);
    int*   idx_s = (int*)(smc + F_IDX);
    uint32_t aBase = s2u(smc);
    uint32_t aSA = aBase + F_SA, aRG = aBase + F_RG;
    uint32_t aE = aRG;
    uint32_t aW[2] = {aRG + 18432, aRG + 36864};
    uint32_t aCBB[2] = {aRG, aRG + 34816};

    int t = threadIdx.x, lane = t & 31, wid = t >> 5;
    int wr = wid >> 2, wc = wid & 3;      // 2 row groups (64 rows) x 4 col groups (32)
    int row0 = blockIdx.x * 128;

    // ---- issue wenc chunk 0 ----
#pragma unroll
    for (int i = 0; i < 4; i++) {
        int q = i * 256 + t;
        int row = q >> 3, c16 = q & 7;
        cp16(aW[0] + row * 144 + c16 * 16, g_wenc + (size_t)row * D_IN + c16 * 8);
    }
    cp_commit();

    // ---- emb chunk 0 register prefetch ----
    float2 pe[16];
#pragma unroll
    for (int i = 0; i < 16; i++) {
        int idx = i * 256 + t;
        int row = idx >> 5, cp = idx & 31;
        pe[i] = *(const float2*)(emb + (size_t)(row0 + row) * D_IN + cp * 2);
    }

    // =========== Phase 1: latent = emb @ Wenc^T ===========
    float acc1[4][4][4];
#pragma unroll
    for (int mt = 0; mt < 4; mt++)
#pragma unroll
        for (int nt = 0; nt < 4; nt++)
#pragma unroll
            for (int j = 0; j < 4; j++) acc1[mt][nt][j] = 0.f;

    for (int c = 0; c < 8; c++) {
        cp_wait<0>();
        __syncthreads();
        if (c < 7) {
            int buf = (c + 1) & 1;
#pragma unroll
            for (int i = 0; i < 4; i++) {
                int q = i * 256 + t;
                int row = q >> 3, c16 = q & 7;
                cp16(aW[buf] + row * 144 + c16 * 16,
                     g_wenc + (size_t)row * D_IN + (c + 1) * 64 + c16 * 8);
            }
            cp_commit();
        }
#pragma unroll
        for (int i = 0; i < 16; i++) {
            int idx = i * 256 + t;
            int row = idx >> 5, cp = idx & 31;
            st_bf2(&sE[row * 72 + cp * 2], pe[i].x, pe[i].y);
        }
        if (c < 7) {
#pragma unroll
            for (int i = 0; i < 16; i++) {
                int idx = i * 256 + t;
                int row = idx >> 5, cp = idx & 31;
                pe[i] = *(const float2*)(emb + (size_t)(row0 + row) * D_IN + (c + 1) * 64 + cp * 2);
            }
        }
        __syncthreads();
        uint32_t aWc = aW[c & 1];
#pragma unroll
        for (int kt = 0; kt < 4; kt++) {
            uint32_t af[4][4], bfr[2][4];
#pragma unroll
            for (int mt = 0; mt < 4; mt++)
                ldsm4(af[mt], aE + ((wr * 64 + mt * 16 + (lane & 15)) * 72
                                    + kt * 16 + (lane >> 4) * 8) * 2);
#pragma unroll
            for (int np = 0; np < 2; np++) {
                int n = wc * 32 + np * 16 + (lane & 7) + ((lane >> 4) & 1) * 8;
                ldsm4(bfr[np], aWc + (n * 72 + kt * 16 + ((lane >> 3) & 1) * 8) * 2);
            }
#pragma unroll
            for (int mt = 0; mt < 4; mt++)
#pragma unroll
                for (int np = 0; np < 2; np++) {
                    mma16816(acc1[mt][2 * np],     af[mt], &bfr[np][0]);
                    mma16816(acc1[mt][2 * np + 1], af[mt], &bfr[np][2]);
                }
        }
    }
    __syncthreads();          // all MMAs done reading RG
    // latent -> sA
#pragma unroll
    for (int mt = 0; mt < 4; mt++)
#pragma unroll
        for (int nt = 0; nt < 4; nt++) {
            int row = wr * 64 + mt * 16 + (lane >> 2);
            int col = wc * 32 + nt * 8 + (lane & 3) * 2;
            st_bf2(&sA[row * 136 + col],       acc1[mt][nt][0], acc1[mt][nt][1]);
            st_bf2(&sA[(row + 8) * 136 + col], acc1[mt][nt][2], acc1[mt][nt][3]);
        }
    // issue cb slabs 0 (codes 0-127) and 1 (codes 128-255) of level 0
#pragma unroll
    for (int j0 = 0; j0 < 2; j0++) {
#pragma unroll
        for (int i = 0; i < 8; i++) {
            int q = i * 256 + t;
            int row = q >> 4, c16 = q & 15;
            cp16(aCBB[j0] + row * 272 + c16 * 16,
                 g_cb + (size_t)(j0 * 128 + row) * DH + c16 * 8);
        }
        cp_commit();
    }

    // =========== Phase 2: 3-level RQ, 128-code slabs ===========
    float rql = 0.f;
    const float* cbs[3] = {cb0, cb1, cb2};
    float best[8]; int bidx[8];

    for (int j = 0; j < 6; j++) {
        int L = j >> 1, h = j & 1;
        uint32_t aCBc = aCBB[j & 1];
        cp_wait<1>();
        if (h == 0) cn_s[t] = g_cn[L * NCODE + t];
        __syncthreads();      // slab visible; cn ready
        if (h == 0) {
#pragma unroll
            for (int s = 0; s < 8; s++) { best[s] = 3.4e38f; bidx[s] = 0; }
        }

        float acc[4][4][4];
#pragma unroll
        for (int mt = 0; mt < 4; mt++)
#pragma unroll
            for (int nt = 0; nt < 4; nt++)
#pragma unroll
                for (int q = 0; q < 4; q++) acc[mt][nt][q] = 0.f;
#pragma unroll
        for (int kt = 0; kt < 8; kt++) {
            uint32_t af[4][4], bfr[2][4];
#pragma unroll
            for (int mt = 0; mt < 4; mt++)
                ldsm4(af[mt], aSA + ((wr * 64 + mt * 16 + (lane & 15)) * 136
                                     + kt * 16 + (lane >> 4) * 8) * 2);
#pragma unroll
            for (int np = 0; np < 2; np++) {
                int n = wc * 32 + np * 16 + (lane & 7) + ((lane >> 4) & 1) * 8;
                ldsm4(bfr[np], aCBc + (n * 136 + kt * 16 + ((lane >> 3) & 1) * 8) * 2);
            }
#pragma unroll
            for (int mt = 0; mt < 4; mt++)
#pragma unroll
                for (int np = 0; np < 2; np++) {
                    mma16816(acc[mt][2 * np],     af[mt], &bfr[np][0]);
                    mma16816(acc[mt][2 * np + 1], af[mt], &bfr[np][2]);
                }
        }
#pragma unroll
        for (int mt = 0; mt < 4; mt++)
#pragma unroll
            for (int nt = 0; nt < 4; nt++) {
                int col = h * 128 + wc * 32 + nt * 8 + (lane & 3) * 2;
                float c0 = cn_s[col], c1 = cn_s[col + 1];
#pragma unroll
                for (int hi = 0; hi < 2; hi++) {
                    int s = mt * 2 + hi;
                    float k0 = fmaf(-2.f, acc[mt][nt][hi * 2],     c0);
                    float k1 = fmaf(-2.f, acc[mt][nt][hi * 2 + 1], c1);
                    if (k0 < best[s]) { best[s] = k0; bidx[s] = col; }
                    if (k1 < best[s]) { best[s] = k1; bidx[s] = col + 1; }
                }
            }
        __syncthreads();      // buffer free to overwrite
        if (j + 2 < 6) {      // next cb slab -> this buffer
#pragma unroll
            for (int i = 0; i < 8; i++) {
                int q = i * 256 + t;
                int row = q >> 4, c16 = q & 15;
                cp16(aCBc + row * 272 + c16 * 16,
                     g_cb + (size_t)((j + 2) >> 1) * NCODE * DH
                          + (size_t)(((j + 2) & 1) * 128 + row) * DH + c16 * 8);
            }
            cp_commit();
        } else {              // wdec pass (j-4) -> this buffer
            int p = j - 4;
#pragma unroll
            for (int i = 0; i < 8; i++) {
                int q = i * 256 + t;
                int row = q >> 4, c16 = q & 15;
                cp16(aCBB[p & 1] + row * 272 + c16 * 16,
                     g_wdec + (size_t)(p * 128 + row) * DH + c16 * 8);
            }
            cp_commit();
        }

        if (h == 1) {
            const float* cbg = cbs[L];
#pragma unroll
            for (int s = 0; s < 8; s++) {
                float bv = best[s]; int bi = bidx[s];
#pragma unroll
                for (int off = 1; off < 4; off <<= 1) {
                    float ov = __shfl_xor_sync(0xffffffffu, bv, off);
                    int   oi = __shfl_xor_sync(0xffffffffu, bi, off);
                    if (ov < bv || (ov == bv && oi < bi)) { bv = ov; bi = oi; }
                }
                if ((lane & 3) == 0) {
                    int row = wr * 64 + (s >> 1) * 16 + (s & 1) * 8 + (lane >> 2);
                    bestv[wc * 128 + row] = bv;
                    besti[wc * 128 + row] = bi;
                }
            }
            __syncthreads();
            if (t < 128) {
                float bv = bestv[t]; int bi = besti[t];
#pragma unroll
                for (int w = 1; w < 4; w++) {
                    float ov = bestv[w * 128 + t]; int oi = besti[w * 128 + t];
                    if (ov < bv || (ov == bv && oi < bi)) { bv = ov; bi = oi; }
                }
                idx_s[L * 128 + t] = bi;
                g_used[L * NCODE + bi] = 1;
            }
            __syncthreads();
            // remainder update; at final level write restored instead of rem
#pragma unroll
            for (int i = 0; i < 16; i++) {
                int r = wid * 16 + i;
                int ci = idx_s[L * 128 + r];
                float4 cv = *(const float4*)(cbg + (size_t)ci * DH + lane * 4);
                uint32_t p0 = *(uint32_t*)&sA[r * 136 + lane * 4];
                uint32_t p1 = *(uint32_t*)&sA[r * 136 + lane * 4 + 2];
                __nv_bfloat162 b0 = *(__nv_bfloat162*)&p0;
                __nv_bfloat162 b1 = *(__nv_bfloat162*)&p1;
                float n0 = __low2float(b0)  - cv.x;
                float n1 = __high2float(b0) - cv.y;
                float n2 = __low2float(b1)  - cv.z;
                float n3 = __high2float(b1) - cv.w;
                rql += n0 * n0 + n1 * n1 + n2 * n2 + n3 * n3;
                if (L < 2) {
                    st_bf2(&sA[r * 136 + lane * 4],     n0, n1);
                    st_bf2(&sA[r * 136 + lane * 4 + 2], n2, n3);
                } else {
                    int i0 = idx_s[r], i1 = idx_s[128 + r];
                    float4 a0 = *(const float4*)(cb0 + (size_t)i0 * DH + lane * 4);
                    float4 a1 = *(const float4*)(cb1 + (size_t)i1 * DH + lane * 4);
                    st_bf2(&sA[r * 136 + lane * 4],
                           a0.x + a1.x + cv.x, a0.y + a1.y + cv.y);
                    st_bf2(&sA[r * 136 + lane * 4 + 2],
                           a0.z + a1.z + cv.z, a0.w + a1.w + cv.w);
                }
            }
        }
    }

    // =========== Phase 3: recon GEMM + fused MSE (4 passes of 128 N) ===========
    float local = 0.f;
    for (int p = 0; p < 4; p++) {
        uint32_t aDc = aCBB[p & 1];
        cp_wait<1>();
        __syncthreads();      // slab visible; sA restored visible (p=0)
        float accR[4][4][4];
#pragma unroll
        for (int mt = 0; mt < 4; mt++)
#pragma unroll
            for (int nt = 0; nt < 4; nt++)
#pragma unroll
                for (int q = 0; q < 4; q++) accR[mt][nt][q] = 0.f;
#pragma unroll
        for (int kt = 0; kt < 8; kt++) {
            uint32_t af[4][4], bfr[2][4];
#pragma unroll
            for (int mt = 0; mt < 4; mt++)
                ldsm4(af[mt], aSA + ((wr * 64 + mt * 16 + (lane & 15)) * 136
                                     + kt * 16 + (lane >> 4) * 8) * 2);
#pragma unroll
            for (int np = 0; np < 2; np++) {
                int n = wc * 32 + np * 16 + (lane & 7) + ((lane >> 4) & 1) * 8;
                ldsm4(bfr[np], aDc + (n * 136 + kt * 16 + ((lane >> 3) & 1) * 8) * 2);
            }
#pragma unroll
            for (int mt = 0; mt < 4; mt++)
#pragma unroll
                for (int np = 0; np < 2; np++) {
                    mma16816(accR[mt][2 * np],     af[mt], &bfr[np][0]);
                    mma16816(accR[mt][2 * np + 1], af[mt], &bfr[np][2]);
                }
        }
        __syncthreads();      // done reading buffer
        if (p + 2 < 4) {
#pragma unroll
            for (int i = 0; i < 8; i++) {
                int q = i * 256 + t;
                int row = q >> 4, c16 = q & 15;
                cp16(aDc + row * 272 + c16 * 16,
                     g_wdec + (size_t)((p + 2) * 128 + row) * DH + c16 * 8);
            }
            cp_commit();
        }
#pragma unroll
        for (int mt = 0; mt < 4; mt++)
#pragma unroll
            for (int nt = 0; nt < 4; nt++) {
                int row = row0 + wr * 64 + mt * 16 + (lane >> 2);
                int col = p * 128 + wc * 32 + nt * 8 + (lane & 3) * 2;
                float2 e0 = *(const float2*)(emb + (size_t)row * D_IN + col);
                float2 e1 = *(const float2*)(emb + (size_t)(row + 8) * D_IN + col);
                float d0 = accR[mt][nt][0] - e0.x;
                float d1 = accR[mt][nt][1] - e0.y;
                float d2 = accR[mt][nt][2] - e1.x;
                float d3 = accR[mt][nt][3] - e1.y;
                local += d0 * d0 + d1 * d1 + d2 * d2 + d3 * d3;
            }
    }

    // ---- reductions ----
#pragma unroll
    for (int off = 16; off > 0; off >>= 1) {
        rql   += __shfl_xor_sync(0xffffffffu, rql, off);
        local += __shfl_xor_sync(0xffffffffu, local, off);
    }
    if (lane == 0) {
        atomicAdd(&g_rq, (double)rql);
        atomicAdd(&g_recon, (double)local);
    }
}

// ---------------- finalize ----------------
__global__ void k_finalize(float* __restrict__ out, int out_size) {
    __shared__ int cnt[3];
    int t = threadIdx.x;
    if (t < 3) cnt[t] = 0;
    __syncthreads();
    if (t < 3 * NCODE) { if (g_used[t]) atomicAdd(&cnt[t / NCODE], 1); }
    __syncthreads();
    if (t == 0) {
        double recon = g_recon / ((double)NROWS * (double)D_IN);
        double rq    = (1.0 + BETA) * g_rq / ((double)NROWS * (double)DH);
        float rf = (float)recon, qf = (float)rq;
        if (out_size > 0) out[0] = rf + qf;
        if (out_size > 1) out[1] = rf;
        if (out_size > 2) out[2] = qf;
        if (out_size > 3) out[3] = (float)cnt[0];
        if (out_size > 4) out[4] = (float)cnt[1];
        if (out_size > 5) out[5] = (float)cnt[2];
    }
    for (int i = 6 + t; i < out_size; i += blockDim.x) out[i] = 0.f;
}

// ---------------- launch ----------------
extern "C" void kernel_launch(void* const* d_in, const int* in_sizes, int n_in,
                              void* d_out, int out_size) {
    const float* emb  = (const float*)d_in[0];
    const float* Wenc = (const float*)d_in[1];
    const float* Wdec = (const float*)d_in[2];
    const float* cb0  = (const float*)d_in[3];
    const float* cb1  = (const float*)d_in[4];
    const float* cb2  = (const float*)d_in[5];

    cudaFuncSetAttribute(k_fused, cudaFuncAttributeMaxDynamicSharedMemorySize, F_SMEM);

    k_init<<<1, 768>>>();
    k_norms<<<3, 256>>>(cb0, cb1, cb2);
    k_cvt<<<448, 256>>>(Wenc, Wdec, cb0, cb1, cb2);
    k_fused<<<NROWS / 128, 256, F_SMEM>>>(emb, cb0, cb1, cb2);
    k_finalize<<<1, 768>>>((float*)d_out, out_size);
}

// round 13
// speedup vs baseline: 1.1872x; 1.0365x over previous
#include <cuda_runtime.h>
#include <cuda_bf16.h>
#include <cstdint>

#define NROWS   131072
#define D_IN    512
#define DH      128
#define NCODE   256
#define BETA    0.25

// ---------------- scratch ----------------
__device__ __nv_bfloat16  g_wenc[(size_t)DH * D_IN];      // 128 x 512
__device__ __nv_bfloat16  g_wdec[(size_t)D_IN * DH];      // 512 x 128
__device__ __nv_bfloat16  g_cb[3 * NCODE * DH];           // 3 x 256 x 128
__device__ float          g_cn[3 * NCODE];
__device__ double g_rq;
__device__ double g_recon;
__device__ int    g_used[3 * NCODE];

// ---------------- helpers ----------------
__device__ __forceinline__ uint32_t s2u(const void* p) {
    uint32_t a;
    asm("{ .reg .u64 t; cvta.to.shared.u64 t, %1; cvt.u32.u64 %0, t; }" : "=r"(a) : "l"(p));
    return a;
}
__device__ __forceinline__ void ldsm4(uint32_t* r, uint32_t addr) {
    asm volatile("ldmatrix.sync.aligned.m8n8.x4.shared.b16 {%0,%1,%2,%3}, [%4];"
        : "=r"(r[0]), "=r"(r[1]), "=r"(r[2]), "=r"(r[3]) : "r"(addr));
}
__device__ __forceinline__ void mma16816(float* c, const uint32_t* a, const uint32_t* b) {
    asm volatile("mma.sync.aligned.m16n8k16.row.col.f32.bf16.bf16.f32 "
        "{%0,%1,%2,%3}, {%4,%5,%6,%7}, {%8,%9}, {%0,%1,%2,%3};"
        : "+f"(c[0]), "+f"(c[1]), "+f"(c[2]), "+f"(c[3])
        : "r"(a[0]), "r"(a[1]), "r"(a[2]), "r"(a[3]), "r"(b[0]), "r"(b[1]));
}
__device__ __forceinline__ void st_bf2(__nv_bfloat16* p, float a, float b) {
    __nv_bfloat162 v = __floats2bfloat162_rn(a, b);
    *(uint32_t*)p = *(uint32_t*)&v;
}
__device__ __forceinline__ uint32_t pack_bf2(float a, float b) {
    __nv_bfloat162 v = __floats2bfloat162_rn(a, b);
    return *(uint32_t*)&v;
}
__device__ __forceinline__ void cp16(uint32_t dst, const void* src) {
    asm volatile("cp.async.cg.shared.global [%0], [%1], 16;" :: "r"(dst), "l"(src));
}
__device__ __forceinline__ void cp_commit() {
    asm volatile("cp.async.commit_group;" ::: "memory");
}
template<int N> __device__ __forceinline__ void cp_wait() {
    asm volatile("cp.async.wait_group %0;" :: "n"(N) : "memory");
}

// ---------------- init / norms / convert ----------------
__global__ void k_init() {
    int t = threadIdx.x;
    if (t == 0) { g_rq = 0.0; g_recon = 0.0; }
    if (t < 3 * NCODE) g_used[t] = 0;
}
__global__ void k_norms(const float* __restrict__ cb0,
                        const float* __restrict__ cb1,
                        const float* __restrict__ cb2) {
    const float* cbs[3] = {cb0, cb1, cb2};
    const float* cb = cbs[blockIdx.x];
    int t = threadIdx.x;
    float s = 0.f;
#pragma unroll
    for (int q = 0; q < 32; q++) {
        float4 v = *(const float4*)(cb + (size_t)t * DH + q * 4);
        s += v.x * v.x + v.y * v.y + v.z * v.z + v.w * v.w;
    }
    g_cn[blockIdx.x * NCODE + t] = s;
}
__global__ void k_cvt(const float* __restrict__ we, const float* __restrict__ wd,
                      const float* __restrict__ c0, const float* __restrict__ c1,
                      const float* __restrict__ c2) {
    int i = blockIdx.x * 256 + threadIdx.x;
    const float* src; uint32_t* dst; int off;
    if (i < 32768)       { src = we; dst = (uint32_t*)g_wenc;         off = i; }
    else if (i < 65536)  { src = wd; dst = (uint32_t*)g_wdec;         off = i - 32768; }
    else if (i < 81920)  { src = c0; dst = (uint32_t*)g_cb;           off = i - 65536; }
    else if (i < 98304)  { src = c1; dst = (uint32_t*)g_cb + 16384;   off = i - 81920; }
    else                 { src = c2; dst = (uint32_t*)g_cb + 32768;   off = i - 98304; }
    float2 v = ((const float2*)src)[off];
    __nv_bfloat162 p = __floats2bfloat162_rn(v.x, v.y);
    dst[off] = *(uint32_t*)&p;
}

// =========================================================================
// Fused kernel, 128 rows/CTA, 256 thr (2 row-groups x 4 col-groups),
// warp tile 64x32, 2 CTAs/SM. One barrier per pipeline iteration.
// smem map (bytes):
//  sA (rem -> restored, bf16 128x136) @ 0       34816
//  RG @ 34816 (73728):
//     GEMM1: ebuf0 @+0, ebuf1 @+18432 (128x72 elem, 144B stride)
//            wbuf0 @+36864, wbuf1 @+55296 (128x72 elem)
//     RQ/recon: cbbuf0 @+0, cbbuf1 @+36864 (128x136 elem, 272B stride)
//  bestv f32[4][128] @ 108544 2048
//  besti i32[4][128] @ 110592 2048  (besti[0..127] doubles as final idx)
//  idx01 i32[2][128] @ 112640 1024
// total 113664 -> 2 CTAs/SM
// =========================================================================
#define F_SA   0
#define F_RG   34816
#define F_BV   108544
#define F_BI   110592
#define F_IDX  112640
#define F_SMEM 113664

__global__ __launch_bounds__(256, 2) void k_fused(const float* __restrict__ emb,
                                                  const float* __restrict__ cb0,
                                                  const float* __restrict__ cb1,
                                                  const float* __restrict__ cb2) {
    extern __shared__ char smc[];
    __nv_bfloat16* sA = (__nv_bfloat16*)(smc + F_SA);
    float* bestv = (float*)(smc + F_BV);
    int*   besti = (int*)(smc + F_BI);
    int*   idx01 = (int*)(smc + F_IDX);
    uint32_t aBase = s2u(smc);
    uint32_t aSA = aBase + F_SA, aRG = aBase + F_RG;
    uint32_t aE[2] = {aRG, aRG + 18432};
    uint32_t aW[2] = {aRG + 36864, aRG + 55296};
    uint32_t aCBB[2] = {aRG, aRG + 36864};

    int t = threadIdx.x, lane = t & 31, wid = t >> 5;
    int wr = wid >> 2, wc = wid & 3;      // 2 row groups (64 rows) x 4 col groups (32)
    int row0 = blockIdx.x * 128;

    // ---- pre-loop: wenc chunk0, emb chunk0 regs + stage, emb chunk1 regs ----
#pragma unroll
    for (int i = 0; i < 4; i++) {
        int q = i * 256 + t;
        int row = q >> 3, c16 = q & 7;
        cp16(aW[0] + row * 144 + c16 * 16, g_wenc + (size_t)row * D_IN + c16 * 8);
    }
    cp_commit();

    float4 pe4[4][2];
#pragma unroll
    for (int i = 0; i < 4; i++) {
        int s = i * 256 + t;
        int row = s >> 3, cb8 = s & 7;
        const float* p = emb + (size_t)(row0 + row) * D_IN + cb8 * 8;
        pe4[i][0] = *(const float4*)p;
        pe4[i][1] = *(const float4*)(p + 4);
    }
#pragma unroll
    for (int i = 0; i < 4; i++) {                 // stage chunk 0 -> ebuf0
        int s = i * 256 + t;
        int row = s >> 3, cb8 = s & 7;
        uint4 u;
        u.x = pack_bf2(pe4[i][0].x, pe4[i][0].y);
        u.y = pack_bf2(pe4[i][0].z, pe4[i][0].w);
        u.z = pack_bf2(pe4[i][1].x, pe4[i][1].y);
        u.w = pack_bf2(pe4[i][1].z, pe4[i][1].w);
        *(uint4*)(smc + F_RG + row * 144 + cb8 * 16) = u;
    }
#pragma unroll
    for (int i = 0; i < 4; i++) {                 // prefetch chunk 1
        int s = i * 256 + t;
        int row = s >> 3, cb8 = s & 7;
        const float* p = emb + (size_t)(row0 + row) * D_IN + 64 + cb8 * 8;
        pe4[i][0] = *(const float4*)p;
        pe4[i][1] = *(const float4*)(p + 4);
    }

    // =========== Phase 1: latent = emb @ Wenc^T ===========
    float acc1[4][4][4];
#pragma unroll
    for (int mt = 0; mt < 4; mt++)
#pragma unroll
        for (int nt = 0; nt < 4; nt++)
#pragma unroll
            for (int j = 0; j < 4; j++) acc1[mt][nt][j] = 0.f;

    for (int c = 0; c < 8; c++) {
        cp_wait<0>();
        __syncthreads();      // ebuf[c&1]+wbuf[c&1] ready; buffers (c+1)&1 free
        if (c < 7) {          // wenc chunk c+1
#pragma unroll
            for (int i = 0; i < 4; i++) {
                int q = i * 256 + t;
                int row = q >> 3, c16 = q & 7;
                cp16(aW[(c + 1) & 1] + row * 144 + c16 * 16,
                     g_wenc + (size_t)row * D_IN + (c + 1) * 64 + c16 * 8);
            }
            cp_commit();
            // stage emb chunk c+1 from regs
#pragma unroll
            for (int i = 0; i < 4; i++) {
                int s = i * 256 + t;
                int row = s >> 3, cb8 = s & 7;
                uint4 u;
                u.x = pack_bf2(pe4[i][0].x, pe4[i][0].y);
                u.y = pack_bf2(pe4[i][0].z, pe4[i][0].w);
                u.z = pack_bf2(pe4[i][1].x, pe4[i][1].y);
                u.w = pack_bf2(pe4[i][1].z, pe4[i][1].w);
                *(uint4*)(smc + F_RG + ((c + 1) & 1) * 18432 + row * 144 + cb8 * 16) = u;
            }
        }
        if (c < 6) {          // prefetch emb chunk c+2
#pragma unroll
            for (int i = 0; i < 4; i++) {
                int s = i * 256 + t;
                int row = s >> 3, cb8 = s & 7;
                const float* p = emb + (size_t)(row0 + row) * D_IN + (c + 2) * 64 + cb8 * 8;
                pe4[i][0] = *(const float4*)p;
                pe4[i][1] = *(const float4*)(p + 4);
            }
        }
        uint32_t aEc = aE[c & 1], aWc = aW[c & 1];
#pragma unroll
        for (int kt = 0; kt < 4; kt++) {
            uint32_t af[4][4], bfr[2][4];
#pragma unroll
            for (int mt = 0; mt < 4; mt++)
                ldsm4(af[mt], aEc + ((wr * 64 + mt * 16 + (lane & 15)) * 72
                                     + kt * 16 + (lane >> 4) * 8) * 2);
#pragma unroll
            for (int np = 0; np < 2; np++) {
                int n = wc * 32 + np * 16 + (lane & 7) + ((lane >> 4) & 1) * 8;
                ldsm4(bfr[np], aWc + (n * 72 + kt * 16 + ((lane >> 3) & 1) * 8) * 2);
            }
#pragma unroll
            for (int mt = 0; mt < 4; mt++)
#pragma unroll
                for (int np = 0; np < 2; np++) {
                    mma16816(acc1[mt][2 * np],     af[mt], &bfr[np][0]);
                    mma16816(acc1[mt][2 * np + 1], af[mt], &bfr[np][2]);
                }
        }
    }
    __syncthreads();          // all MMAs done reading RG
    // latent -> sA
#pragma unroll
    for (int mt = 0; mt < 4; mt++)
#pragma unroll
        for (int nt = 0; nt < 4; nt++) {
            int row = wr * 64 + mt * 16 + (lane >> 2);
            int col = wc * 32 + nt * 8 + (lane & 3) * 2;
            st_bf2(&sA[row * 136 + col],       acc1[mt][nt][0], acc1[mt][nt][1]);
            st_bf2(&sA[(row + 8) * 136 + col], acc1[mt][nt][2], acc1[mt][nt][3]);
        }
    // issue cb level-0 slab 0 -> cbbuf0
#pragma unroll
    for (int i = 0; i < 8; i++) {
        int q = i * 256 + t;
        int row = q >> 4, c16 = q & 15;
        cp16(aCBB[0] + row * 272 + c16 * 16, g_cb + (size_t)row * DH + c16 * 8);
    }
    cp_commit();

    // =========== Phase 2: 3-level RQ, 128-code slabs ===========
    float rql = 0.f;
    const float* cbs[3] = {cb0, cb1, cb2};
    float best[8]; int bidx[8];

    for (int j = 0; j < 6; j++) {
        int L = j >> 1, h = j & 1;
        uint32_t aCBc = aCBB[j & 1];
        cp_wait<0>();
        __syncthreads();      // slab j ready; sA update of prior level visible
        if (j < 5) {          // issue slab j+1 -> other buffer
#pragma unroll
            for (int i = 0; i < 8; i++) {
                int q = i * 256 + t;
                int row = q >> 4, c16 = q & 15;
                cp16(aCBB[(j + 1) & 1] + row * 272 + c16 * 16,
                     g_cb + (size_t)((j + 1) >> 1) * NCODE * DH
                          + (size_t)(((j + 1) & 1) * 128 + row) * DH + c16 * 8);
            }
            cp_commit();
        } else {              // issue wdec chunk 0 -> cbbuf0
#pragma unroll
            for (int i = 0; i < 8; i++) {
                int q = i * 256 + t;
                int row = q >> 4, c16 = q & 15;
                cp16(aCBB[0] + row * 272 + c16 * 16, g_wdec + (size_t)row * DH + c16 * 8);
            }
            cp_commit();
        }
        if (h == 0) {
#pragma unroll
            for (int s = 0; s < 8; s++) { best[s] = 3.4e38f; bidx[s] = 0; }
        }
        // code norms for this thread's 8 columns (L2-resident, hidden under MMA)
        float2 cnv[4];
#pragma unroll
        for (int nt = 0; nt < 4; nt++)
            cnv[nt] = *(const float2*)(g_cn + L * NCODE + h * 128 + wc * 32
                                       + nt * 8 + (lane & 3) * 2);

        float acc[4][4][4];
#pragma unroll
        for (int mt = 0; mt < 4; mt++)
#pragma unroll
            for (int nt = 0; nt < 4; nt++)
#pragma unroll
                for (int q = 0; q < 4; q++) acc[mt][nt][q] = 0.f;
#pragma unroll
        for (int kt = 0; kt < 8; kt++) {
            uint32_t af[4][4], bfr[2][4];
#pragma unroll
            for (int mt = 0; mt < 4; mt++)
                ldsm4(af[mt], aSA + ((wr * 64 + mt * 16 + (lane & 15)) * 136
                                     + kt * 16 + (lane >> 4) * 8) * 2);
#pragma unroll
            for (int np = 0; np < 2; np++) {
                int n = wc * 32 + np * 16 + (lane & 7) + ((lane >> 4) & 1) * 8;
                ldsm4(bfr[np], aCBc + (n * 136 + kt * 16 + ((lane >> 3) & 1) * 8) * 2);
            }
#pragma unroll
            for (int mt = 0; mt < 4; mt++)
#pragma unroll
                for (int np = 0; np < 2; np++) {
                    mma16816(acc[mt][2 * np],     af[mt], &bfr[np][0]);
                    mma16816(acc[mt][2 * np + 1], af[mt], &bfr[np][2]);
                }
        }
#pragma unroll
        for (int mt = 0; mt < 4; mt++)
#pragma unroll
            for (int nt = 0; nt < 4; nt++) {
                int col = h * 128 + wc * 32 + nt * 8 + (lane & 3) * 2;
#pragma unroll
                for (int hi = 0; hi < 2; hi++) {
                    int s = mt * 2 + hi;
                    float k0 = fmaf(-2.f, acc[mt][nt][hi * 2],     cnv[nt].x);
                    float k1 = fmaf(-2.f, acc[mt][nt][hi * 2 + 1], cnv[nt].y);
                    if (k0 < best[s]) { best[s] = k0; bidx[s] = col; }
                    if (k1 < best[s]) { best[s] = k1; bidx[s] = col + 1; }
                }
            }

        if (h == 1) {
            const float* cbg = cbs[L];
#pragma unroll
            for (int s = 0; s < 8; s++) {
                float bv = best[s]; int bi = bidx[s];
#pragma unroll
                for (int off = 1; off < 4; off <<= 1) {
                    float ov = __shfl_xor_sync(0xffffffffu, bv, off);
                    int   oi = __shfl_xor_sync(0xffffffffu, bi, off);
                    if (ov < bv || (ov == bv && oi < bi)) { bv = ov; bi = oi; }
                }
                if ((lane & 3) == 0) {
                    int row = wr * 64 + (s >> 1) * 16 + (s & 1) * 8 + (lane >> 2);
                    bestv[wc * 128 + row] = bv;
                    besti[wc * 128 + row] = bi;
                }
            }
            __syncthreads();
            if (t < 128) {
                float bv = bestv[t]; int bi = besti[t];
#pragma unroll
                for (int w = 1; w < 4; w++) {
                    float ov = bestv[w * 128 + t]; int oi = besti[w * 128 + t];
                    if (ov < bv || (ov == bv && oi < bi)) { bv = ov; bi = oi; }
                }
                besti[t] = bi;                    // final index for this level
                if (L < 2) idx01[L * 128 + t] = bi;
                g_used[L * NCODE + bi] = 1;
            }
            __syncthreads();
            // remainder update; final level writes restored
#pragma unroll
            for (int i = 0; i < 16; i++) {
                int r = wid * 16 + i;
                int ci = besti[r];
                float4 cv = *(const float4*)(cbg + (size_t)ci * DH + lane * 4);
                uint32_t p0 = *(uint32_t*)&sA[r * 136 + lane * 4];
                uint32_t p1 = *(uint32_t*)&sA[r * 136 + lane * 4 + 2];
                __nv_bfloat162 b0 = *(__nv_bfloat162*)&p0;
                __nv_bfloat162 b1 = *(__nv_bfloat162*)&p1;
                float n0 = __low2float(b0)  - cv.x;
                float n1 = __high2float(b0) - cv.y;
                float n2 = __low2float(b1)  - cv.z;
                float n3 = __high2float(b1) - cv.w;
                rql += n0 * n0 + n1 * n1 + n2 * n2 + n3 * n3;
                if (L < 2) {
                    st_bf2(&sA[r * 136 + lane * 4],     n0, n1);
                    st_bf2(&sA[r * 136 + lane * 4 + 2], n2, n3);
                } else {
                    int i0 = idx01[r], i1 = idx01[128 + r];
                    float4 a0 = *(const float4*)(cb0 + (size_t)i0 * DH + lane * 4);
                    float4 a1 = *(const float4*)(cb1 + (size_t)i1 * DH + lane * 4);
                    st_bf2(&sA[r * 136 + lane * 4],
                           a0.x + a1.x + cv.x, a0.y + a1.y + cv.y);
                    st_bf2(&sA[r * 136 + lane * 4 + 2],
                           a0.z + a1.z + cv.z, a0.w + a1.w + cv.w);
                }
            }
        }
    }

    // =========== Phase 3: recon GEMM + fused MSE (4 passes of 128 N) ===========
    float local = 0.f;
    for (int p = 0; p < 4; p++) {
        uint32_t aDc = aCBB[p & 1];
        cp_wait<0>();
        __syncthreads();      // wdec chunk p ready; sA restored visible (p=0)
        if (p < 3) {          // issue wdec chunk p+1
#pragma unroll
            for (int i = 0; i < 8; i++) {
                int q = i * 256 + t;
                int row = q >> 4, c16 = q & 15;
                cp16(aCBB[(p + 1) & 1] + row * 272 + c16 * 16,
                     g_wdec + (size_t)((p + 1) * 128 + row) * DH + c16 * 8);
            }
            cp_commit();
        }
        float accR[4][4][4];
#pragma unroll
        for (int mt = 0; mt < 4; mt++)
#pragma unroll
            for (int nt = 0; nt < 4; nt++)
#pragma unroll
                for (int q = 0; q < 4; q++) accR[mt][nt][q] = 0.f;
#pragma unroll
        for (int kt = 0; kt < 8; kt++) {
            uint32_t af[4][4], bfr[2][4];
#pragma unroll
            for (int mt = 0; mt < 4; mt++)
                ldsm4(af[mt], aSA + ((wr * 64 + mt * 16 + (lane & 15)) * 136
                                     + kt * 16 + (lane >> 4) * 8) * 2);
#pragma unroll
            for (int np = 0; np < 2; np++) {
                int n = wc * 32 + np * 16 + (lane & 7) + ((lane >> 4) & 1) * 8;
                ldsm4(bfr[np], aDc + (n * 136 + kt * 16 + ((lane >> 3) & 1) * 8) * 2);
            }
#pragma unroll
            for (int mt = 0; mt < 4; mt++)
#pragma unroll
                for (int np = 0; np < 2; np++) {
                    mma16816(accR[mt][2 * np],     af[mt], &bfr[np][0]);
                    mma16816(accR[mt][2 * np + 1], af[mt], &bfr[np][2]);
                }
        }
#pragma unroll
        for (int mt = 0; mt < 4; mt++)
#pragma unroll
            for (int nt = 0; nt < 4; nt++) {
                int row = row0 + wr * 64 + mt * 16 + (lane >> 2);
                int col = p * 128 + wc * 32 + nt * 8 + (lane & 3) * 2;
                float2 e0 = *(const float2*)(emb + (size_t)row * D_IN + col);
                float2 e1 = *(const float2*)(emb + (size_t)(row + 8) * D_IN + col);
                float d0 = accR[mt][nt][0] - e0.x;
                float d1 = accR[mt][nt][1] - e0.y;
                float d2 = accR[mt][nt][2] - e1.x;
                float d3 = accR[mt][nt][3] - e1.y;
                local += d0 * d0 + d1 * d1 + d2 * d2 + d3 * d3;
            }
    }

    // ---- reductions ----
#pragma unroll
    for (int off = 16; off > 0; off >>= 1) {
        rql   += __shfl_xor_sync(0xffffffffu, rql, off);
        local += __shfl_xor_sync(0xffffffffu, local, off);
    }
    if (lane == 0) {
        atomicAdd(&g_rq, (double)rql);
        atomicAdd(&g_recon, (double)local);
    }
}

// ---------------- finalize ----------------
__global__ void k_finalize(float* __restrict__ out, int out_size) {
    __shared__ int cnt[3];
    int t = threadIdx.x;
    if (t < 3) cnt[t] = 0;
    __syncthreads();
    if (t < 3 * NCODE) { if (g_used[t]) atomicAdd(&cnt[t / NCODE], 1); }
    __syncthreads();
    if (t == 0) {
        double recon = g_recon / ((double)NROWS * (double)D_IN);
        double rq    = (1.0 + BETA) * g_rq / ((double)NROWS * (double)DH);
        float rf = (float)recon, qf = (float)rq;
        if (out_size > 0) out[0] = rf + qf;
        if (out_size > 1) out[1] = rf;
        if (out_size > 2) out[2] = qf;
        if (out_size > 3) out[3] = (float)cnt[0];
        if (out_size > 4) out[4] = (float)cnt[1];
        if (out_size > 5) out[5] = (float)cnt[2];
    }
    for (int i = 6 + t; i < out_size; i += blockDim.x) out[i] = 0.f;
}

// ---------------- launch ----------------
extern "C" void kernel_launch(void* const* d_in, const int* in_sizes, int n_in,
                              void* d_out, int out_size) {
    const float* emb  = (const float*)d_in[0];
    const float* Wenc = (const float*)d_in[1];
    const float* Wdec = (const float*)d_in[2];
    const float* cb0  = (const float*)d_in[3];
    const float* cb1  = (const float*)d_in[4];
    const float* cb2  = (const float*)d_in[5];

    cudaFuncSetAttribute(k_fused, cudaFuncAttributeMaxDynamicSharedMemorySize, F_SMEM);

    k_init<<<1, 768>>>();
    k_norms<<<3, 256>>>(cb0, cb1, cb2);
    k_cvt<<<448, 256>>>(Wenc, Wdec, cb0, cb1, cb2);
    k_fused<<<NROWS / 128, 256, F_SMEM>>>(emb, cb0, cb1, cb2);
    k_finalize<<<1, 768>>>((float*)d_out, out_size);
}